// round 15
// baseline (speedup 1.0000x reference)
#include <cuda_runtime.h>
#include <cuda_fp16.h>
#include <cuda_bf16.h>
#include <cstdint>

#define EMB 128
#define PRED_IN 532
#define MAX_NODES 131072
#define MAX_REL 1024
#define RPB 8

// mma table kernel geometry (fused: one block does M=64 nodes x N=256, 512 threads)
#define KTOT 144            // 128 he + 10 pe + 6 pad
#define NTOT 256
#define MT 64               // nodes per block
#define XSTRIDE 152         // half stride (conflict-free ldmatrix)
#define X_SMEM_BYTES (MT * XSTRIDE * 2)            // 19456
#define W_SMEM_BYTES (NTOT * XSTRIDE * 2)          // 77824
#define SMEM_BYTES (X_SMEM_BYTES + W_SMEM_BYTES)   // 97280 (2/SM = 190KB <= 228KB)

// ---------------- scratch ----------------
__device__ __align__(16) __half g_Ah[MAX_NODES * EMB];
__device__ __align__(16) __half g_Bh[MAX_NODES * EMB];
__device__ __align__(16) __half g_Rmh[MAX_REL * EMB];
__device__ __align__(16) __half g_Wt16[NTOT * KTOT];      // [n][k] fp16 combined weights
__device__ __align__(16) float g_WTq[EMB * EMB];
__device__ __align__(16) float g_WTr[EMB * EMB];
__device__ __align__(16) float4 g_scrf[MAX_NODES];        // {sx, sy, deg_t, pad}
__device__ __align__(16) float4 g_scrr[MAX_NODES];        // {sx, sy, deg_h, pad}
__device__ __align__(16) float2 g_d[4][MAX_NODES];

// ---------------- kernels ----------------

__global__ void k_prep_init(const float* __restrict__ W1, int n_nodes) {
    int idx = blockIdx.x * blockDim.x + threadIdx.x;
    if (idx < n_nodes) {
        g_scrf[idx] = make_float4(0.f, 0.f, 0.f, 0.f);
        g_scrr[idx] = make_float4(0.f, 0.f, 0.f, 0.f);
    }
    if (idx < EMB * EMB) {
        int k = idx >> 7;
        int i = idx & 127;
        const float* row = W1 + i * PRED_IN;
        g_WTq[idx] = row[k];
        g_WTr[idx] = row[266 + k];
    }
    if (idx < NTOT * KTOT) {
        int n = idx / KTOT;
        int k = idx % KTOT;
        int j = n & 127;
        const float* row = W1 + j * PRED_IN;
        float v = 0.f;
        if (n < 128) {
            if (k < 128) v = row[128 + k];
            else if (k < 138) v = row[256 + (k - 128)];
        } else {
            if (k < 128) v = row[394 + k];
            else if (k < 138) v = row[522 + (k - 128)];
        }
        g_Wt16[idx] = __float2half_rn(v);
    }
}

// Rm[r][i] = b1[i] + W1q.q + W1r.rel[r]; fp16 store
__global__ __launch_bounds__(EMB) void k_rm(const float* __restrict__ q,
                                            const float* __restrict__ rel,
                                            const float* __restrict__ b1, int n_rel) {
    __shared__ float qs[EMB];
    __shared__ float rs[RPB][EMB];
    int i = threadIdx.x;
    int rbase = blockIdx.x * RPB;
    qs[i] = q[i];
    #pragma unroll
    for (int r = 0; r < RPB; r++) {
        int rid = rbase + r;
        rs[r][i] = (rid < n_rel) ? rel[rid * EMB + i] : 0.f;
    }
    __syncthreads();
    float accq = b1[i];
    float acc[RPB];
    #pragma unroll
    for (int r = 0; r < RPB; r++) acc[r] = 0.f;
    #pragma unroll 4
    for (int k = 0; k < EMB; k++) {
        float wq = g_WTq[k * EMB + i];
        float wr = g_WTr[k * EMB + i];
        accq += wq * qs[k];
        #pragma unroll
        for (int r = 0; r < RPB; r++) acc[r] += wr * rs[r][k];
    }
    #pragma unroll
    for (int r = 0; r < RPB; r++) {
        int rid = rbase + r;
        if (rid < n_rel) g_Rmh[rid * EMB + i] = __float2half_rn(accq + acc[r]);
    }
}

// Round 1: degrees + fwd (topic[h]->t) + rev (topic[t]->h)
__global__ void k_sc1(const float2* __restrict__ topic, const int* __restrict__ h_id,
                      const int* __restrict__ t_id, int E) {
    int e = blockIdx.x * blockDim.x + threadIdx.x;
    if (e < E) {
        int h = h_id[e];
        int t = t_id[e];
        float2 vh = topic[h];
        float2 vt = topic[t];
        float4* pf = &g_scrf[t];
        float4* pr = &g_scrr[h];
        asm volatile("red.global.add.v4.f32 [%0], {%1, %2, %3, %4};"
                     :: "l"(pf), "f"(vh.x), "f"(vh.y), "f"(1.f), "f"(0.f) : "memory");
        asm volatile("red.global.add.v4.f32 [%0], {%1, %2, %3, %4};"
                     :: "l"(pr), "f"(vt.x), "f"(vt.y), "f"(1.f), "f"(0.f) : "memory");
    }
}

__global__ void k_norm2d(int fo, int ro, int last, int n_nodes) {
    int i = blockIdx.x * blockDim.x + threadIdx.x;
    if (i < n_nodes) {
        float4 sf = g_scrf[i];
        float4 sr = g_scrr[i];
        float ct = fmaxf(sf.z, 1.f);
        float ch = fmaxf(sr.z, 1.f);
        g_d[fo][i] = make_float2(sf.x / ct, sf.y / ct);
        g_d[ro][i] = make_float2(sr.x / ch, sr.y / ch);
        if (!last) {
            g_scrf[i] = make_float4(0.f, 0.f, sf.z, 0.f);
            g_scrr[i] = make_float4(0.f, 0.f, sr.z, 0.f);
        }
    }
}

__global__ void k_sc2(const int* __restrict__ h_id, const int* __restrict__ t_id, int E) {
    int e = blockIdx.x * blockDim.x + threadIdx.x;
    if (e < E) {
        int h = h_id[e];
        int t = t_id[e];
        float2 vh = g_d[0][h];
        float2 vt = g_d[2][t];
        float* pf = &g_scrf[t].x;
        float* pr = &g_scrr[h].x;
        asm volatile("red.global.add.v2.f32 [%0], {%1, %2};"
                     :: "l"(pf), "f"(vh.x), "f"(vh.y) : "memory");
        asm volatile("red.global.add.v2.f32 [%0], {%1, %2};"
                     :: "l"(pr), "f"(vt.x), "f"(vt.y) : "memory");
    }
}

// Node tables via tensor cores: block = M=64 nodes x N=256 (A||B), 512 threads / 16 warps.
// Warp w owns n-cols [16w, 16w+16). acc = 4mt x 2nt x 4 = 32 regs/thread.
__global__ __launch_bounds__(512, 2) void k_tab_mma(
    const float* __restrict__ ent, const float* __restrict__ nte,
    const float* __restrict__ topic, int n_text, int n_nodes) {
    extern __shared__ char smem[];
    __half* Xs = (__half*)smem;                       // [MT][XSTRIDE]
    __half* Ws = (__half*)(smem + X_SMEM_BYTES);      // [NTOT][XSTRIDE]
    int tid = threadIdx.x;
    int base = blockIdx.x * MT;

    // ---- stage weights: g_Wt16 [256][144] -> Ws [256][152] ----
    for (int idx = tid; idx < NTOT * 18; idx += 512) {
        int n = idx / 18;
        int c = idx % 18;
        uint4 v = ((const uint4*)g_Wt16)[n * 18 + c];
        *(uint4*)&Ws[n * XSTRIDE + c * 8] = v;
    }

    // ---- stage X: he part ----
    for (int idx = tid; idx < MT * 32; idx += 512) {
        int m = idx / 32;
        int c = idx % 32;
        int id = base + m;
        float4 v = make_float4(0.f, 0.f, 0.f, 0.f);
        if (id < n_text) v = ((const float4*)ent)[id * 32 + c];
        else if (id < n_nodes) v = ((const float4*)nte)[c];
        __half2 h0 = __floats2half2_rn(v.x, v.y);
        __half2 h1 = __floats2half2_rn(v.z, v.w);
        *(__half2*)&Xs[m * XSTRIDE + c * 4] = h0;
        *(__half2*)&Xs[m * XSTRIDE + c * 4 + 2] = h1;
    }
    // ---- stage X: pe part, cols 128..143 ----
    for (int idx = tid; idx < MT * 16; idx += 512) {
        int m = idx / 16;
        int j = idx % 16;
        int id = base + m;
        float v = 0.f;
        if (id < n_nodes) {
            if (j < 2) v = topic[id * 2 + j];
            else if (j < 10) {
                int rr = (j - 2) >> 1;
                float2 d = g_d[rr][id];
                v = (j & 1) ? d.y : d.x;
            }
        }
        Xs[m * XSTRIDE + 128 + j] = __float2half_rn(v);
    }
    __syncthreads();

    int lane = tid & 31;
    int warp = tid >> 5;                // 0..15
    int nb = warp * 16;                 // warp's 16-col slice within N=256

    uint32_t x_base = (uint32_t)__cvta_generic_to_shared(Xs);
    uint32_t w_base = (uint32_t)__cvta_generic_to_shared(Ws);

    int a_row_off = (lane & 7) + ((lane & 8) ? 8 : 0);
    int a_col_off = (lane & 16) ? 8 : 0;
    int b_row_off = lane & 7;
    int b_col_off = (lane & 8) ? 8 : 0;

    float acc[4][2][4];
    #pragma unroll
    for (int mt = 0; mt < 4; mt++)
        #pragma unroll
        for (int nt = 0; nt < 2; nt++)
            #pragma unroll
            for (int c = 0; c < 4; c++) acc[mt][nt][c] = 0.f;

    #pragma unroll
    for (int ks = 0; ks < 9; ks++) {
        int k0 = ks * 16;
        uint32_t b[2][2];
        #pragma unroll
        for (int nt = 0; nt < 2; nt++) {
            uint32_t addr = w_base +
                (uint32_t)(((nb + nt * 8 + b_row_off) * XSTRIDE + k0 + b_col_off) * 2);
            asm volatile("ldmatrix.sync.aligned.m8n8.x2.shared.b16 {%0,%1}, [%2];"
                         : "=r"(b[nt][0]), "=r"(b[nt][1]) : "r"(addr));
        }
        #pragma unroll
        for (int mt = 0; mt < 4; mt++) {
            uint32_t a0, a1, a2, a3;
            uint32_t addr = x_base +
                (uint32_t)(((mt * 16 + a_row_off) * XSTRIDE + k0 + a_col_off) * 2);
            asm volatile("ldmatrix.sync.aligned.m8n8.x4.shared.b16 {%0,%1,%2,%3}, [%4];"
                         : "=r"(a0), "=r"(a1), "=r"(a2), "=r"(a3) : "r"(addr));
            #pragma unroll
            for (int nt = 0; nt < 2; nt++) {
                asm volatile(
                    "mma.sync.aligned.m16n8k16.row.col.f32.f16.f16.f32 "
                    "{%0,%1,%2,%3}, {%4,%5,%6,%7}, {%8,%9}, {%0,%1,%2,%3};"
                    : "+f"(acc[mt][nt][0]), "+f"(acc[mt][nt][1]),
                      "+f"(acc[mt][nt][2]), "+f"(acc[mt][nt][3])
                    : "r"(a0), "r"(a1), "r"(a2), "r"(a3),
                      "r"(b[nt][0]), "r"(b[nt][1]));
            }
        }
    }

    int g = lane >> 2;
    int t4 = lane & 3;
    #pragma unroll
    for (int mt = 0; mt < 4; mt++) {
        int row0 = base + mt * 16 + g;
        int row1 = row0 + 8;
        #pragma unroll
        for (int nt = 0; nt < 2; nt++) {
            int n = nb + nt * 8 + 2 * t4;
            __half* dst = (n < 128) ? g_Ah : g_Bh;
            int col = n & 127;
            __half2 lo = __floats2half2_rn(acc[mt][nt][0], acc[mt][nt][1]);
            __half2 hi = __floats2half2_rn(acc[mt][nt][2], acc[mt][nt][3]);
            if (row0 < n_nodes) *(__half2*)&dst[row0 * EMB + col] = lo;
            if (row1 < n_nodes) *(__half2*)&dst[row1 * EMB + col] = hi;
        }
    }
}

// Edge combine: 4 edges per warp (8 lanes each, 16 fp16 dims per lane via 2 uint4).
__global__ __launch_bounds__(256) void k_edge(
    const int* __restrict__ h_id, const int* __restrict__ r_id, const int* __restrict__ t_id,
    const float* __restrict__ W2, const float* __restrict__ b2,
    float* __restrict__ out, int E) {
    int gw = (blockIdx.x * blockDim.x + threadIdx.x) >> 5;
    int lane = threadIdx.x & 31;
    int qe = lane >> 3;                 // edge slot 0..3 within warp
    int hl = lane & 7;                  // lane within 8-lane group
    int e = gw * 4 + qe;
    bool valid = (e < E);
    int ei = valid ? e : 0;
    int h = h_id[ei];
    int t = t_id[ei];
    int r = r_id[ei];
    const uint4* A4 = (const uint4*)g_Ah;   // row = 16 uint4; lane covers 2*hl, 2*hl+1
    const uint4* B4 = (const uint4*)g_Bh;
    const uint4* R4 = (const uint4*)g_Rmh;
    uint4 ua0 = A4[h * 16 + 2 * hl];
    uint4 ua1 = A4[h * 16 + 2 * hl + 1];
    uint4 ub0 = B4[t * 16 + 2 * hl];
    uint4 ub1 = B4[t * 16 + 2 * hl + 1];
    uint4 uc0 = R4[r * 16 + 2 * hl];
    uint4 uc1 = R4[r * 16 + 2 * hl + 1];
    const float4* W24 = (const float4*)W2;

    float s = 0.f;
    {
        const uint32_t* pa = &ua0.x;
        const uint32_t* pb = &ub0.x;
        const uint32_t* pc = &uc0.x;
        #pragma unroll
        for (int i = 0; i < 4; i++) {
            float2 av = __half22float2(*(const __half2*)&pa[i]);
            float2 bv = __half22float2(*(const __half2*)&pb[i]);
            float2 cv = __half22float2(*(const __half2*)&pc[i]);
            float2 wv = (i & 1) ? make_float2(W24[hl * 4 + (i >> 1)].z, W24[hl * 4 + (i >> 1)].w)
                                : make_float2(W24[hl * 4 + (i >> 1)].x, W24[hl * 4 + (i >> 1)].y);
            s += wv.x * fmaxf(av.x + bv.x + cv.x, 0.f)
               + wv.y * fmaxf(av.y + bv.y + cv.y, 0.f);
        }
        const uint32_t* pa1 = &ua1.x;
        const uint32_t* pb1 = &ub1.x;
        const uint32_t* pc1 = &uc1.x;
        #pragma unroll
        for (int i = 0; i < 4; i++) {
            float2 av = __half22float2(*(const __half2*)&pa1[i]);
            float2 bv = __half22float2(*(const __half2*)&pb1[i]);
            float2 cv = __half22float2(*(const __half2*)&pc1[i]);
            float2 wv = (i & 1) ? make_float2(W24[hl * 4 + 2 + (i >> 1)].z, W24[hl * 4 + 2 + (i >> 1)].w)
                                : make_float2(W24[hl * 4 + 2 + (i >> 1)].x, W24[hl * 4 + 2 + (i >> 1)].y);
            s += wv.x * fmaxf(av.x + bv.x + cv.x, 0.f)
               + wv.y * fmaxf(av.y + bv.y + cv.y, 0.f);
        }
    }
    #pragma unroll
    for (int off = 4; off; off >>= 1) s += __shfl_xor_sync(0xFFFFFFFFu, s, off);
    if (valid && hl == 0) out[ei] = s + b2[0];
}

// ---------------- launch ----------------

extern "C" void kernel_launch(void* const* d_in, const int* in_sizes, int n_in,
                              void* d_out, int out_size) {
    const int*   h_id  = (const int*)d_in[0];
    const int*   r_id  = (const int*)d_in[1];
    const int*   t_id  = (const int*)d_in[2];
    const float* q     = (const float*)d_in[3];
    const float* ent   = (const float*)d_in[4];
    const float* rel   = (const float*)d_in[6];
    const float* topic = (const float*)d_in[7];
    const float* nte   = (const float*)d_in[8];
    const float* W1    = (const float*)d_in[9];
    const float* b1    = (const float*)d_in[10];
    const float* W2    = (const float*)d_in[11];
    const float* b2    = (const float*)d_in[12];
    float* out = (float*)d_out;

    int E       = in_sizes[0];
    int n_text  = in_sizes[4] / EMB;
    int n_rel   = in_sizes[6] / EMB;
    int n_nodes = in_sizes[7] / 2;

    const int T = 256;
    int nb_nodes = (n_nodes + T - 1) / T;
    int nb_edges = (E + T - 1) / T;
    int prep_n = n_nodes > NTOT * KTOT ? n_nodes : NTOT * KTOT;

    static int smem_set = 0;
    if (!smem_set) {
        cudaFuncSetAttribute(k_tab_mma, cudaFuncAttributeMaxDynamicSharedMemorySize,
                             SMEM_BYTES);
        smem_set = 1;
    }

    const float2* topic2 = (const float2*)topic;

    k_prep_init<<<(prep_n + T - 1) / T, T>>>(W1, n_nodes);
    k_rm<<<(n_rel + RPB - 1) / RPB, EMB>>>(q, rel, b1, n_rel);
    k_sc1<<<nb_edges, T>>>(topic2, h_id, t_id, E);
    k_norm2d<<<nb_nodes, T>>>(0, 2, 0, n_nodes);
    k_sc2<<<nb_edges, T>>>(h_id, t_id, E);
    k_norm2d<<<nb_nodes, T>>>(1, 3, 1, n_nodes);

    int nb_tab = (n_nodes + MT - 1) / MT;
    k_tab_mma<<<nb_tab, 512, SMEM_BYTES>>>(ent, nte, topic, n_text, n_nodes);

    int n_warps = (E + 3) / 4;
    int nb_e = (n_warps + 7) / 8;
    k_edge<<<nb_e, T>>>(h_id, r_id, t_id, W2, b2, out, E);
}

// round 16
// speedup vs baseline: 1.1994x; 1.1994x over previous
#include <cuda_runtime.h>
#include <cuda_fp16.h>
#include <cuda_bf16.h>
#include <cstdint>

#define EMB 128
#define PRED_IN 532
#define MAX_NODES 131072
#define MAX_REL 1024
#define RPB 8

// mma table kernel geometry: one block does 2 M-tiles of 64 nodes x N=256, 512 threads
#define KTOT 144            // 128 he + 10 pe + 6 pad
#define NTOT 256
#define MT 64               // nodes per M-tile
#define MTILES 2            // M-tiles per block
#define XSTRIDE 152         // half stride (conflict-free ldmatrix)
#define X_SMEM_BYTES (MT * XSTRIDE * 2)            // 19456
#define W_SMEM_BYTES (NTOT * XSTRIDE * 2)          // 77824
#define SMEM_BYTES (X_SMEM_BYTES + W_SMEM_BYTES)   // 97280 (2/SM = 190KB <= 228KB)

// ---------------- scratch ----------------
__device__ __align__(16) __half g_Ah[MAX_NODES * EMB];
__device__ __align__(16) __half g_Bh[MAX_NODES * EMB];
__device__ __align__(16) __half g_Rmh[MAX_REL * EMB];
__device__ __align__(16) __half g_Wt16[NTOT * KTOT];      // [n][k] fp16 combined weights
__device__ __align__(16) float g_WTq[EMB * EMB];
__device__ __align__(16) float g_WTr[EMB * EMB];
__device__ __align__(16) float4 g_scrf[MAX_NODES];        // {sx, sy, deg_t, pad}
__device__ __align__(16) float4 g_scrr[MAX_NODES];        // {sx, sy, deg_h, pad}
__device__ __align__(16) float2 g_d[4][MAX_NODES];

// ---------------- kernels ----------------

__global__ void k_prep_init(const float* __restrict__ W1, int n_nodes) {
    int idx = blockIdx.x * blockDim.x + threadIdx.x;
    if (idx < n_nodes) {
        g_scrf[idx] = make_float4(0.f, 0.f, 0.f, 0.f);
        g_scrr[idx] = make_float4(0.f, 0.f, 0.f, 0.f);
    }
    if (idx < EMB * EMB) {
        int k = idx >> 7;
        int i = idx & 127;
        const float* row = W1 + i * PRED_IN;
        g_WTq[idx] = row[k];
        g_WTr[idx] = row[266 + k];
    }
    if (idx < NTOT * KTOT) {
        int n = idx / KTOT;
        int k = idx % KTOT;
        int j = n & 127;
        const float* row = W1 + j * PRED_IN;
        float v = 0.f;
        if (n < 128) {
            if (k < 128) v = row[128 + k];
            else if (k < 138) v = row[256 + (k - 128)];
        } else {
            if (k < 128) v = row[394 + k];
            else if (k < 138) v = row[522 + (k - 128)];
        }
        g_Wt16[idx] = __float2half_rn(v);
    }
}

// Rm[r][i] = b1[i] + W1q.q + W1r.rel[r]; fp16 store
__global__ __launch_bounds__(EMB) void k_rm(const float* __restrict__ q,
                                            const float* __restrict__ rel,
                                            const float* __restrict__ b1, int n_rel) {
    __shared__ float qs[EMB];
    __shared__ float rs[RPB][EMB];
    int i = threadIdx.x;
    int rbase = blockIdx.x * RPB;
    qs[i] = q[i];
    #pragma unroll
    for (int r = 0; r < RPB; r++) {
        int rid = rbase + r;
        rs[r][i] = (rid < n_rel) ? rel[rid * EMB + i] : 0.f;
    }
    __syncthreads();
    float accq = b1[i];
    float acc[RPB];
    #pragma unroll
    for (int r = 0; r < RPB; r++) acc[r] = 0.f;
    #pragma unroll 4
    for (int k = 0; k < EMB; k++) {
        float wq = g_WTq[k * EMB + i];
        float wr = g_WTr[k * EMB + i];
        accq += wq * qs[k];
        #pragma unroll
        for (int r = 0; r < RPB; r++) acc[r] += wr * rs[r][k];
    }
    #pragma unroll
    for (int r = 0; r < RPB; r++) {
        int rid = rbase + r;
        if (rid < n_rel) g_Rmh[rid * EMB + i] = __float2half_rn(accq + acc[r]);
    }
}

// Round 1: degrees + fwd (topic[h]->t) + rev (topic[t]->h)
__global__ void k_sc1(const float2* __restrict__ topic, const int* __restrict__ h_id,
                      const int* __restrict__ t_id, int E) {
    int e = blockIdx.x * blockDim.x + threadIdx.x;
    if (e < E) {
        int h = h_id[e];
        int t = t_id[e];
        float2 vh = topic[h];
        float2 vt = topic[t];
        float4* pf = &g_scrf[t];
        float4* pr = &g_scrr[h];
        asm volatile("red.global.add.v4.f32 [%0], {%1, %2, %3, %4};"
                     :: "l"(pf), "f"(vh.x), "f"(vh.y), "f"(1.f), "f"(0.f) : "memory");
        asm volatile("red.global.add.v4.f32 [%0], {%1, %2, %3, %4};"
                     :: "l"(pr), "f"(vt.x), "f"(vt.y), "f"(1.f), "f"(0.f) : "memory");
    }
}

__global__ void k_norm2d(int fo, int ro, int last, int n_nodes) {
    int i = blockIdx.x * blockDim.x + threadIdx.x;
    if (i < n_nodes) {
        float4 sf = g_scrf[i];
        float4 sr = g_scrr[i];
        float ct = fmaxf(sf.z, 1.f);
        float ch = fmaxf(sr.z, 1.f);
        g_d[fo][i] = make_float2(sf.x / ct, sf.y / ct);
        g_d[ro][i] = make_float2(sr.x / ch, sr.y / ch);
        if (!last) {
            g_scrf[i] = make_float4(0.f, 0.f, sf.z, 0.f);
            g_scrr[i] = make_float4(0.f, 0.f, sr.z, 0.f);
        }
    }
}

__global__ void k_sc2(const int* __restrict__ h_id, const int* __restrict__ t_id, int E) {
    int e = blockIdx.x * blockDim.x + threadIdx.x;
    if (e < E) {
        int h = h_id[e];
        int t = t_id[e];
        float2 vh = g_d[0][h];
        float2 vt = g_d[2][t];
        float* pf = &g_scrf[t].x;
        float* pr = &g_scrr[h].x;
        asm volatile("red.global.add.v2.f32 [%0], {%1, %2};"
                     :: "l"(pf), "f"(vh.x), "f"(vh.y) : "memory");
        asm volatile("red.global.add.v2.f32 [%0], {%1, %2};"
                     :: "l"(pr), "f"(vt.x), "f"(vt.y) : "memory");
    }
}

// Node tables via tensor cores: block = 2 M-tiles x (M=64 x N=256), 512 threads / 16 warps.
// Weights staged ONCE per block; X restaged per tile. acc = 32 regs/thread.
__global__ __launch_bounds__(512, 2) void k_tab_mma(
    const float* __restrict__ ent, const float* __restrict__ nte,
    const float* __restrict__ topic, int n_text, int n_nodes) {
    extern __shared__ char smem[];
    __half* Xs = (__half*)smem;                       // [MT][XSTRIDE]
    __half* Ws = (__half*)(smem + X_SMEM_BYTES);      // [NTOT][XSTRIDE]
    int tid = threadIdx.x;
    int lane = tid & 31;
    int warp = tid >> 5;                // 0..15
    int nb = warp * 16;                 // warp's 16-col slice within N=256

    // ---- stage weights once: g_Wt16 [256][144] -> Ws [256][152] ----
    for (int idx = tid; idx < NTOT * 18; idx += 512) {
        int n = idx / 18;
        int c = idx % 18;
        uint4 v = ((const uint4*)g_Wt16)[n * 18 + c];
        *(uint4*)&Ws[n * XSTRIDE + c * 8] = v;
    }

    uint32_t x_base = (uint32_t)__cvta_generic_to_shared(Xs);
    uint32_t w_base = (uint32_t)__cvta_generic_to_shared(Ws);

    int a_row_off = (lane & 7) + ((lane & 8) ? 8 : 0);
    int a_col_off = (lane & 16) ? 8 : 0;
    int b_row_off = lane & 7;
    int b_col_off = (lane & 8) ? 8 : 0;
    int g = lane >> 2;
    int t4 = lane & 3;

    #pragma unroll
    for (int mtile = 0; mtile < MTILES; mtile++) {
        int base = (blockIdx.x * MTILES + mtile) * MT;

        // ---- stage X: he part ----
        for (int idx = tid; idx < MT * 32; idx += 512) {
            int m = idx / 32;
            int c = idx % 32;
            int id = base + m;
            float4 v = make_float4(0.f, 0.f, 0.f, 0.f);
            if (id < n_text) v = ((const float4*)ent)[id * 32 + c];
            else if (id < n_nodes) v = ((const float4*)nte)[c];
            __half2 h0 = __floats2half2_rn(v.x, v.y);
            __half2 h1 = __floats2half2_rn(v.z, v.w);
            *(__half2*)&Xs[m * XSTRIDE + c * 4] = h0;
            *(__half2*)&Xs[m * XSTRIDE + c * 4 + 2] = h1;
        }
        // ---- stage X: pe part, cols 128..143 ----
        for (int idx = tid; idx < MT * 16; idx += 512) {
            int m = idx / 16;
            int j = idx % 16;
            int id = base + m;
            float v = 0.f;
            if (id < n_nodes) {
                if (j < 2) v = topic[id * 2 + j];
                else if (j < 10) {
                    int rr = (j - 2) >> 1;
                    float2 d = g_d[rr][id];
                    v = (j & 1) ? d.y : d.x;
                }
            }
            Xs[m * XSTRIDE + 128 + j] = __float2half_rn(v);
        }
        __syncthreads();

        float acc[4][2][4];
        #pragma unroll
        for (int mt = 0; mt < 4; mt++)
            #pragma unroll
            for (int nt = 0; nt < 2; nt++)
                #pragma unroll
                for (int c = 0; c < 4; c++) acc[mt][nt][c] = 0.f;

        #pragma unroll
        for (int ks = 0; ks < 9; ks++) {
            int k0 = ks * 16;
            uint32_t b[2][2];
            #pragma unroll
            for (int nt = 0; nt < 2; nt++) {
                uint32_t addr = w_base +
                    (uint32_t)(((nb + nt * 8 + b_row_off) * XSTRIDE + k0 + b_col_off) * 2);
                asm volatile("ldmatrix.sync.aligned.m8n8.x2.shared.b16 {%0,%1}, [%2];"
                             : "=r"(b[nt][0]), "=r"(b[nt][1]) : "r"(addr));
            }
            #pragma unroll
            for (int mt = 0; mt < 4; mt++) {
                uint32_t a0, a1, a2, a3;
                uint32_t addr = x_base +
                    (uint32_t)(((mt * 16 + a_row_off) * XSTRIDE + k0 + a_col_off) * 2);
                asm volatile("ldmatrix.sync.aligned.m8n8.x4.shared.b16 {%0,%1,%2,%3}, [%4];"
                             : "=r"(a0), "=r"(a1), "=r"(a2), "=r"(a3) : "r"(addr));
                #pragma unroll
                for (int nt = 0; nt < 2; nt++) {
                    asm volatile(
                        "mma.sync.aligned.m16n8k16.row.col.f32.f16.f16.f32 "
                        "{%0,%1,%2,%3}, {%4,%5,%6,%7}, {%8,%9}, {%0,%1,%2,%3};"
                        : "+f"(acc[mt][nt][0]), "+f"(acc[mt][nt][1]),
                          "+f"(acc[mt][nt][2]), "+f"(acc[mt][nt][3])
                        : "r"(a0), "r"(a1), "r"(a2), "r"(a3),
                          "r"(b[nt][0]), "r"(b[nt][1]));
                }
            }
        }

        #pragma unroll
        for (int mt = 0; mt < 4; mt++) {
            int row0 = base + mt * 16 + g;
            int row1 = row0 + 8;
            #pragma unroll
            for (int nt = 0; nt < 2; nt++) {
                int n = nb + nt * 8 + 2 * t4;
                __half* dst = (n < 128) ? g_Ah : g_Bh;
                int col = n & 127;
                __half2 lo = __floats2half2_rn(acc[mt][nt][0], acc[mt][nt][1]);
                __half2 hi = __floats2half2_rn(acc[mt][nt][2], acc[mt][nt][3]);
                if (row0 < n_nodes) *(__half2*)&dst[row0 * EMB + col] = lo;
                if (row1 < n_nodes) *(__half2*)&dst[row1 * EMB + col] = hi;
            }
        }
        if (mtile + 1 < MTILES) __syncthreads();   // protect Xs before restaging
    }
}

// Edge combine: 2 edges per warp (16 lanes each, 8 fp16 dims per lane).
__global__ __launch_bounds__(256) void k_edge(
    const int* __restrict__ h_id, const int* __restrict__ r_id, const int* __restrict__ t_id,
    const float* __restrict__ W2, const float* __restrict__ b2,
    float* __restrict__ out, int E) {
    int gw = (blockIdx.x * blockDim.x + threadIdx.x) >> 5;
    int lane = threadIdx.x & 31;
    int half = lane >> 4;
    int hl = lane & 15;
    int e = gw * 2 + half;
    bool valid = (e < E);
    int ei = valid ? e : 0;
    int h = h_id[ei];
    int t = t_id[ei];
    int r = r_id[ei];
    const uint4* A4 = (const uint4*)g_Ah;
    const uint4* B4 = (const uint4*)g_Bh;
    const uint4* R4 = (const uint4*)g_Rmh;
    uint4 ua = A4[h * 16 + hl];
    uint4 ub = B4[t * 16 + hl];
    uint4 uc = R4[r * 16 + hl];
    float4 w0 = ((const float4*)W2)[hl * 2];
    float4 w1 = ((const float4*)W2)[hl * 2 + 1];

    float2 a0 = __half22float2(*(const __half2*)&ua.x);
    float2 a1 = __half22float2(*(const __half2*)&ua.y);
    float2 a2 = __half22float2(*(const __half2*)&ua.z);
    float2 a3 = __half22float2(*(const __half2*)&ua.w);
    float2 b0 = __half22float2(*(const __half2*)&ub.x);
    float2 b1v = __half22float2(*(const __half2*)&ub.y);
    float2 b2v = __half22float2(*(const __half2*)&ub.z);
    float2 b3 = __half22float2(*(const __half2*)&ub.w);
    float2 c0 = __half22float2(*(const __half2*)&uc.x);
    float2 c1 = __half22float2(*(const __half2*)&uc.y);
    float2 c2 = __half22float2(*(const __half2*)&uc.z);
    float2 c3 = __half22float2(*(const __half2*)&uc.w);

    float s = w0.x * fmaxf(a0.x + b0.x + c0.x, 0.f)
            + w0.y * fmaxf(a0.y + b0.y + c0.y, 0.f)
            + w0.z * fmaxf(a1.x + b1v.x + c1.x, 0.f)
            + w0.w * fmaxf(a1.y + b1v.y + c1.y, 0.f)
            + w1.x * fmaxf(a2.x + b2v.x + c2.x, 0.f)
            + w1.y * fmaxf(a2.y + b2v.y + c2.y, 0.f)
            + w1.z * fmaxf(a3.x + b3.x + c3.x, 0.f)
            + w1.w * fmaxf(a3.y + b3.y + c3.y, 0.f);
    #pragma unroll
    for (int off = 8; off; off >>= 1) s += __shfl_xor_sync(0xFFFFFFFFu, s, off);
    if (valid && hl == 0) out[ei] = s + b2[0];
}

// ---------------- launch ----------------

extern "C" void kernel_launch(void* const* d_in, const int* in_sizes, int n_in,
                              void* d_out, int out_size) {
    const int*   h_id  = (const int*)d_in[0];
    const int*   r_id  = (const int*)d_in[1];
    const int*   t_id  = (const int*)d_in[2];
    const float* q     = (const float*)d_in[3];
    const float* ent   = (const float*)d_in[4];
    const float* rel   = (const float*)d_in[6];
    const float* topic = (const float*)d_in[7];
    const float* nte   = (const float*)d_in[8];
    const float* W1    = (const float*)d_in[9];
    const float* b1    = (const float*)d_in[10];
    const float* W2    = (const float*)d_in[11];
    const float* b2    = (const float*)d_in[12];
    float* out = (float*)d_out;

    int E       = in_sizes[0];
    int n_text  = in_sizes[4] / EMB;
    int n_rel   = in_sizes[6] / EMB;
    int n_nodes = in_sizes[7] / 2;

    const int T = 256;
    int nb_nodes = (n_nodes + T - 1) / T;
    int nb_edges = (E + T - 1) / T;
    int prep_n = n_nodes > NTOT * KTOT ? n_nodes : NTOT * KTOT;

    static int smem_set = 0;
    if (!smem_set) {
        cudaFuncSetAttribute(k_tab_mma, cudaFuncAttributeMaxDynamicSharedMemorySize,
                             SMEM_BYTES);
        smem_set = 1;
    }

    const float2* topic2 = (const float2*)topic;

    k_prep_init<<<(prep_n + T - 1) / T, T>>>(W1, n_nodes);
    k_rm<<<(n_rel + RPB - 1) / RPB, EMB>>>(q, rel, b1, n_rel);
    k_sc1<<<nb_edges, T>>>(topic2, h_id, t_id, E);
    k_norm2d<<<nb_nodes, T>>>(0, 2, 0, n_nodes);
    k_sc2<<<nb_edges, T>>>(h_id, t_id, E);
    k_norm2d<<<nb_nodes, T>>>(1, 3, 1, n_nodes);

    int nb_tab = (n_nodes + MT * MTILES - 1) / (MT * MTILES);
    k_tab_mma<<<nb_tab, 512, SMEM_BYTES>>>(ent, nte, topic, n_text, n_nodes);

    int n_warps = (E + 1) / 2;
    int nb_e = (n_warps + 7) / 8;
    k_edge<<<nb_e, T>>>(h_id, r_id, t_id, W2, b2, out, E);
}